// round 7
// baseline (speedup 1.0000x reference)
#include <cuda_runtime.h>

// ---------------------------------------------------------------------------
// Routing_2259152797848: capsule routing
// R7: R4 scaffolding + R2-style dual register tiles:
//     phase A = direct dots on float4 tile (no shuffle tree, no SELs, no d_s),
//     phase B = scalar tile + broadcast LDS.128 of p. 2 bars/iter.
// ---------------------------------------------------------------------------

#define MAXN 50016
#define D    128
#define CH   8
#define KD   16
#define M    32

__device__ float g_z[(size_t)(MAXN + 1) * D];
__device__ int   g_is64;

__global__ void k_detect(const int* __restrict__ w) {
    if (threadIdx.x == 0) {
        int any = 0;
        #pragma unroll 8
        for (int i = 0; i < 128; i++) any |= w[2 * i + 1];
        g_is64 = (any == 0) ? 1 : 0;
    }
}

__global__ void k_zero(int n) {
    g_z[(size_t)n * D + threadIdx.x] = 0.0f;
}

// --- FC + relu + per-capsule normalize (unchanged) ----------------------------
__global__ void k_fc(const float* __restrict__ x, const float* __restrict__ W,
                     const float* __restrict__ b, int n) {
    extern __shared__ float smem[];
    float* w_s = smem;             // [128][132]
    float* x_s = smem + 128 * 132; // [32][128]

    const int t = threadIdx.x;
    const int r0 = blockIdx.x * 32;

    const float4* W4 = (const float4*)W;
    float4* ws4 = (float4*)w_s;
    #pragma unroll
    for (int i = 0; i < 32; i++) {
        int idx4 = t + 128 * i;
        int j = idx4 >> 5, kk = idx4 & 31;
        ws4[j * 33 + kk] = W4[idx4];
    }
    const float4* X4 = (const float4*)x;
    float4* xs4 = (float4*)x_s;
    #pragma unroll
    for (int i = 0; i < 8; i++) {
        int idx4 = t + 128 * i;
        int r = idx4 >> 5, kk = idx4 & 31;
        float4 v = make_float4(0.f, 0.f, 0.f, 0.f);
        if (r0 + r < n) v = X4[(size_t)(r0 + r) * 32 + kk];
        xs4[r * 32 + kk] = v;
    }
    __syncthreads();

    const int tx = t & 31;
    const int ty = t >> 5;

    float acc[8][4];
    #pragma unroll
    for (int rr = 0; rr < 8; rr++)
        #pragma unroll
        for (int cc = 0; cc < 4; cc++) acc[rr][cc] = 0.f;

    #pragma unroll 4
    for (int k4 = 0; k4 < 32; k4++) {
        float4 wv[4];
        #pragma unroll
        for (int cc = 0; cc < 4; cc++) wv[cc] = ws4[(tx + 32 * cc) * 33 + k4];
        float4 xr[8];
        #pragma unroll
        for (int rr = 0; rr < 8; rr++) xr[rr] = xs4[(ty + 4 * rr) * 32 + k4];
        #pragma unroll
        for (int rr = 0; rr < 8; rr++)
            #pragma unroll
            for (int cc = 0; cc < 4; cc++) {
                acc[rr][cc] = fmaf(xr[rr].x, wv[cc].x, acc[rr][cc]);
                acc[rr][cc] = fmaf(xr[rr].y, wv[cc].y, acc[rr][cc]);
                acc[rr][cc] = fmaf(xr[rr].z, wv[cc].z, acc[rr][cc]);
                acc[rr][cc] = fmaf(xr[rr].w, wv[cc].w, acc[rr][cc]);
            }
    }

    float bv[4];
    #pragma unroll
    for (int cc = 0; cc < 4; cc++) bv[cc] = b[tx + 32 * cc];

    #pragma unroll
    for (int rr = 0; rr < 8; rr++) {
        int row = r0 + ty + 4 * rr;
        #pragma unroll
        for (int cc = 0; cc < 4; cc++) {
            float v = fmaxf(acc[rr][cc] + bv[cc], 0.f);
            float s = v * v;
            s += __shfl_xor_sync(0xffffffffu, s, 1);
            s += __shfl_xor_sync(0xffffffffu, s, 2);
            s += __shfl_xor_sync(0xffffffffu, s, 4);
            s += __shfl_xor_sync(0xffffffffu, s, 8);
            float inv = rsqrtf(fmaxf(s, 1e-24f));
            if (row < n) g_z[(size_t)row * D + tx + 32 * cc] = v * inv;
        }
    }
}

__device__ __forceinline__ float dot4(float4 a, float4 b) {
    return a.x * b.x + a.y * b.y + a.z * b.z + a.w * b.w;
}

// --- routing: 256 threads = 2 independent nodes -------------------------------
// phase A identity (m0 = tl>>3, cA = tl&7): register tile a0[4],a1[4] =
//   neighbor rows m0, m0+16 of channel cA. d computed by direct dots; softmax
//   happens in the SAME thread (no d_s round-trip).
// phase B identity (c = tl>>4, g = tl&15): scalar tile nbr[32].
__global__ void __launch_bounds__(256, 3)
k_route(const void* __restrict__ nid_raw, float* __restrict__ out, int n) {
    __shared__ __align__(16) float us[2][D];          // u in (c*16+k) layout
    __shared__ __align__(16) float ps[2][CH * 36];    // ps[c*36 + m]
    __shared__ int ids[2][M];

    const int t   = threadIdx.x;
    const int grp = t >> 7;
    const int tl  = t & 127;
    const int bid = 1 + grp;
    const int node = blockIdx.x * 2 + grp;
    if (node >= n) return;
    const int is64 = g_is64;

    if (tl < M) {
        long long id;
        if (is64) id = ((const long long*)nid_raw)[(size_t)node * M + tl];
        else      id = (long long)((const int*)nid_raw)[(size_t)node * M + tl];
        ids[grp][tl] = (int)id;
    }
    const float xc = g_z[(size_t)node * D + tl];
    us[grp][tl] = xc;
    asm volatile("bar.sync %0, %1;" :: "r"(bid), "r"(128) : "memory");

    const int m0 = tl >> 3, cA = tl & 7;   // phase-A / softmax identity
    const int c  = tl >> 4, g  = tl & 15;  // phase-B identity
    (void)g;

    // phase-A register tile: rows m0 and m0+16, channel cA (8 LDG.128)
    const float4* Z4 = (const float4*)g_z;
    float4 a0[4], a1[4];
    {
        size_t r0 = (size_t)ids[grp][m0]      * 32 + (size_t)cA * 4;
        size_t r1 = (size_t)ids[grp][m0 + 16] * 32 + (size_t)cA * 4;
        #pragma unroll
        for (int j = 0; j < 4; j++) { a0[j] = Z4[r0 + j]; a1[j] = Z4[r1 + j]; }
    }
    // phase-B register tile: one (c,k) element of each neighbor (32 LDG.32)
    float nbr[M];
    #pragma unroll
    for (int m = 0; m < M; m++)
        nbr[m] = g_z[(size_t)ids[grp][m] * D + tl];

    const float4* us4 = (const float4*)us[grp];
    float acc;

    for (int it = 0; it < 3; it++) {
        // ---- phase A: direct dots (4 independent partials each) ----
        float4 u0 = us4[cA * 4 + 0], u1 = us4[cA * 4 + 1];
        float4 u2 = us4[cA * 4 + 2], u3 = us4[cA * 4 + 3];
        float d0 = (dot4(u0, a0[0]) + dot4(u1, a0[1])) +
                   (dot4(u2, a0[2]) + dot4(u3, a0[3]));
        float d1 = (dot4(u0, a1[0]) + dot4(u1, a1[1])) +
                   (dot4(u2, a1[2]) + dot4(u3, a1[3]));

        // |d| <= 1 (unit capsules): exp safe without max-subtraction
        float e0 = __expf(d0);
        float e1 = __expf(d1);
        float sm0 = e0, sm1 = e1;   // softmax over c = 8 adjacent lanes
        sm0 += __shfl_xor_sync(0xffffffffu, sm0, 1);
        sm1 += __shfl_xor_sync(0xffffffffu, sm1, 1);
        sm0 += __shfl_xor_sync(0xffffffffu, sm0, 2);
        sm1 += __shfl_xor_sync(0xffffffffu, sm1, 2);
        sm0 += __shfl_xor_sync(0xffffffffu, sm0, 4);
        sm1 += __shfl_xor_sync(0xffffffffu, sm1, 4);
        ps[grp][cA * 36 + m0]      = __fdividef(e0, sm0);
        ps[grp][cA * 36 + m0 + 16] = __fdividef(e1, sm1);
        asm volatile("bar.sync %0, %1;" :: "r"(bid), "r"(128) : "memory");

        // ---- phase B: u[c,k] = x_caps + sum_m p[m,c]*nb[m,c,k] ----
        float c0 = 0.f, c1 = 0.f, c2 = 0.f, c3 = 0.f;
        #pragma unroll
        for (int j = 0; j < 2; j++) {
            float4 p0 = *(const float4*)&ps[grp][c * 36 + 16 * j + 0];
            float4 p1 = *(const float4*)&ps[grp][c * 36 + 16 * j + 4];
            float4 p2 = *(const float4*)&ps[grp][c * 36 + 16 * j + 8];
            float4 p3 = *(const float4*)&ps[grp][c * 36 + 16 * j + 12];
            const float* nb = &nbr[16 * j];
            c0 = fmaf(p0.x, nb[0],  c0); c0 = fmaf(p0.y, nb[1],  c0);
            c0 = fmaf(p0.z, nb[2],  c0); c0 = fmaf(p0.w, nb[3],  c0);
            c1 = fmaf(p1.x, nb[4],  c1); c1 = fmaf(p1.y, nb[5],  c1);
            c1 = fmaf(p1.z, nb[6],  c1); c1 = fmaf(p1.w, nb[7],  c1);
            c2 = fmaf(p2.x, nb[8],  c2); c2 = fmaf(p2.y, nb[9],  c2);
            c2 = fmaf(p2.z, nb[10], c2); c2 = fmaf(p2.w, nb[11], c2);
            c3 = fmaf(p3.x, nb[12], c3); c3 = fmaf(p3.y, nb[13], c3);
            c3 = fmaf(p3.z, nb[14], c3); c3 = fmaf(p3.w, nb[15], c3);
        }
        acc = xc + ((c0 + c1) + (c2 + c3));

        if (it < 2) {
            float sq = acc * acc;
            sq += __shfl_xor_sync(0xffffffffu, sq, 1);
            sq += __shfl_xor_sync(0xffffffffu, sq, 2);
            sq += __shfl_xor_sync(0xffffffffu, sq, 4);
            sq += __shfl_xor_sync(0xffffffffu, sq, 8);
            float u_val = acc * rsqrtf(fmaxf(sq, 1e-24f));
            us[grp][tl] = u_val;
            asm volatile("bar.sync %0, %1;" :: "r"(bid), "r"(128) : "memory");
        } else {
            out[(size_t)node * D + tl] = acc;
        }
    }
}

// ---------------------------------------------------------------------------
extern "C" void kernel_launch(void* const* d_in, const int* in_sizes, int n_in,
                              void* d_out, int out_size) {
    const float* x = (const float*)d_in[0];
    const float* W = (const float*)d_in[1];
    const float* b = (const float*)d_in[2];
    const void*  nid = d_in[3];
    float* out = (float*)d_out;

    int n = in_sizes[0] / D;

    static const size_t FC_SMEM = (size_t)(128 * 132 + 32 * 128) * sizeof(float);
    cudaFuncSetAttribute(k_fc, cudaFuncAttributeMaxDynamicSharedMemorySize,
                         (int)FC_SMEM);

    k_detect<<<1, 32>>>((const int*)nid);
    k_zero<<<1, D>>>(n);
    int nblk = (n + 31) / 32;
    k_fc<<<nblk, 128, FC_SMEM>>>(x, W, b, n);
    k_route<<<(n + 1) / 2, 256>>>(nid, out, n);
}

// round 8
// speedup vs baseline: 1.3688x; 1.3688x over previous
#include <cuda_runtime.h>

// ---------------------------------------------------------------------------
// Routing_2259152797848: capsule routing
// R8 = R4 (best: 272us) + loop-invariant SEL hoisting (partial XOR register
//      permutation, bits 0-1 of the tree) + stage-1 FMA fusion + 4-acc phase B.
// ---------------------------------------------------------------------------

#define MAXN 50016
#define D    128
#define CH   8
#define KD   16
#define M    32

__device__ float g_z[(size_t)(MAXN + 1) * D];
__device__ int   g_is64;

// fused: zero pad row + int64/int32 sniff (odd 32-bit words all zero <=> int64)
__global__ void k_init(const int* __restrict__ w, int n) {
    int t = threadIdx.x;
    if (t < 128) g_z[(size_t)n * D + t] = 0.0f;
    if (t == 128) {
        int any = 0;
        #pragma unroll 8
        for (int i = 0; i < 128; i++) any |= w[2 * i + 1];
        g_is64 = (any == 0) ? 1 : 0;
    }
}

// --- FC + relu + per-capsule normalize (unchanged) ----------------------------
__global__ void k_fc(const float* __restrict__ x, const float* __restrict__ W,
                     const float* __restrict__ b, int n) {
    extern __shared__ float smem[];
    float* w_s = smem;             // [128][132]
    float* x_s = smem + 128 * 132; // [32][128]

    const int t = threadIdx.x;
    const int r0 = blockIdx.x * 32;

    const float4* W4 = (const float4*)W;
    float4* ws4 = (float4*)w_s;
    #pragma unroll
    for (int i = 0; i < 32; i++) {
        int idx4 = t + 128 * i;
        int j = idx4 >> 5, kk = idx4 & 31;
        ws4[j * 33 + kk] = W4[idx4];
    }
    const float4* X4 = (const float4*)x;
    float4* xs4 = (float4*)x_s;
    #pragma unroll
    for (int i = 0; i < 8; i++) {
        int idx4 = t + 128 * i;
        int r = idx4 >> 5, kk = idx4 & 31;
        float4 v = make_float4(0.f, 0.f, 0.f, 0.f);
        if (r0 + r < n) v = X4[(size_t)(r0 + r) * 32 + kk];
        xs4[r * 32 + kk] = v;
    }
    __syncthreads();

    const int tx = t & 31;
    const int ty = t >> 5;

    float acc[8][4];
    #pragma unroll
    for (int rr = 0; rr < 8; rr++)
        #pragma unroll
        for (int cc = 0; cc < 4; cc++) acc[rr][cc] = 0.f;

    #pragma unroll 4
    for (int k4 = 0; k4 < 32; k4++) {
        float4 wv[4];
        #pragma unroll
        for (int cc = 0; cc < 4; cc++) wv[cc] = ws4[(tx + 32 * cc) * 33 + k4];
        float4 xr[8];
        #pragma unroll
        for (int rr = 0; rr < 8; rr++) xr[rr] = xs4[(ty + 4 * rr) * 32 + k4];
        #pragma unroll
        for (int rr = 0; rr < 8; rr++)
            #pragma unroll
            for (int cc = 0; cc < 4; cc++) {
                acc[rr][cc] = fmaf(xr[rr].x, wv[cc].x, acc[rr][cc]);
                acc[rr][cc] = fmaf(xr[rr].y, wv[cc].y, acc[rr][cc]);
                acc[rr][cc] = fmaf(xr[rr].z, wv[cc].z, acc[rr][cc]);
                acc[rr][cc] = fmaf(xr[rr].w, wv[cc].w, acc[rr][cc]);
            }
    }

    float bv[4];
    #pragma unroll
    for (int cc = 0; cc < 4; cc++) bv[cc] = b[tx + 32 * cc];

    #pragma unroll
    for (int rr = 0; rr < 8; rr++) {
        int row = r0 + ty + 4 * rr;
        #pragma unroll
        for (int cc = 0; cc < 4; cc++) {
            float v = fmaxf(acc[rr][cc] + bv[cc], 0.f);
            float s = v * v;
            s += __shfl_xor_sync(0xffffffffu, s, 1);
            s += __shfl_xor_sync(0xffffffffu, s, 2);
            s += __shfl_xor_sync(0xffffffffu, s, 4);
            s += __shfl_xor_sync(0xffffffffu, s, 8);
            float inv = rsqrtf(fmaxf(s, 1e-24f));
            if (row < n) g_z[(size_t)row * D + tx + 32 * cc] = v * inv;
        }
    }
}

// --- routing: 256 threads = 2 independent nodes -------------------------------
// Thread (c = tl>>4, g = tl&15). One coalesced gather: nbrA[q]=nb[2q][c][g],
// nbrB[q]=nb[2q+1][c][g] (R4 order), then one-time conditional register swaps
// implement layout nbr*[j] <- nbr*[j ^ (g&3)], making tree stages 1,2 SEL-free:
//   stage1: s1[i] = fma(u, nbr[2i], shfl(u*nbr[2i+1], 1))
//   stage2: s2[i] = s1[2i] + shfl(s1[2i+1], 2)
//   stages 3,4: R4-style keep/send selects (loop-variant operands).
// Final lane ownership: q_f = (g&3) | ((g&4)<<1) | ((g&8)>>1); lane holds
// d[2*q_f] (A tree) and d[2*q_f+1] (B tree), summed over all 16 k-lanes.
__global__ void __launch_bounds__(256)
k_route(const void* __restrict__ nid_raw, float* __restrict__ out, int n) {
    __shared__ __align__(16) float d_s[2][CH * 36];   // d_s[c*36 + m] (exp'd)
    __shared__ __align__(16) float ps[2][CH * 36];    // ps[c*36 + m]
    __shared__ int ids[2][M];

    const int t   = threadIdx.x;
    const int grp = t >> 7;
    const int tl  = t & 127;
    const int bid = 1 + grp;
    const int node = blockIdx.x * 2 + grp;
    if (node >= n) return;
    const int is64 = g_is64;

    if (tl < M) {
        long long id;
        if (is64) id = ((const long long*)nid_raw)[(size_t)node * M + tl];
        else      id = (long long)((const int*)nid_raw)[(size_t)node * M + tl];
        ids[grp][tl] = (int)id;
    }
    const float xc = g_z[(size_t)node * D + tl];
    asm volatile("bar.sync %0, %1;" :: "r"(bid), "r"(128) : "memory");

    const int c  = tl >> 4, g  = tl & 15;   // tree / phase-B identity
    const int m0 = tl >> 3, cA = tl & 7;    // softmax identity
    const int qf = (g & 3) | ((g & 4) << 1) | ((g & 8) >> 1);

    // one coalesced gather (R4 order: pair q -> rows 2q, 2q+1)
    float nbrA[16], nbrB[16];
    #pragma unroll
    for (int q = 0; q < 16; q++) {
        nbrA[q] = g_z[(size_t)ids[grp][2 * q]     * D + tl];
        nbrB[q] = g_z[(size_t)ids[grp][2 * q + 1] * D + tl];
    }

    // one-time register permutation: nbr*[j] <- nbr*[j ^ (g&3)]
    {
        const bool p0 = (g & 1) != 0;
        #pragma unroll
        for (int i = 0; i < 8; i++) {
            float a = nbrA[2 * i], b = nbrA[2 * i + 1];
            nbrA[2 * i] = p0 ? b : a; nbrA[2 * i + 1] = p0 ? a : b;
            float e = nbrB[2 * i], f = nbrB[2 * i + 1];
            nbrB[2 * i] = p0 ? f : e; nbrB[2 * i + 1] = p0 ? e : f;
        }
        const bool p1 = (g & 2) != 0;
        #pragma unroll
        for (int i = 0; i < 4; i++)
            #pragma unroll
            for (int j = 0; j < 2; j++) {
                int xI = 4 * i + j, yI = 4 * i + j + 2;
                float a = nbrA[xI], b = nbrA[yI];
                nbrA[xI] = p1 ? b : a; nbrA[yI] = p1 ? a : b;
                float e = nbrB[xI], f = nbrB[yI];
                nbrB[xI] = p1 ? f : e; nbrB[yI] = p1 ? e : f;
            }
    }

    float u_val = xc;
    float acc;

    for (int it = 0; it < 3; it++) {
        // ---- stage 1 (SEL-free, FMA-fused) ----
        float sA1[8], sB1[8];
        #pragma unroll
        for (int i = 0; i < 8; i++) {
            float tA = u_val * nbrA[2 * i + 1];
            float tB = u_val * nbrB[2 * i + 1];
            sA1[i] = fmaf(u_val, nbrA[2 * i], __shfl_xor_sync(0xffffffffu, tA, 1));
            sB1[i] = fmaf(u_val, nbrB[2 * i], __shfl_xor_sync(0xffffffffu, tB, 1));
        }
        // ---- stage 2 (SEL-free) ----
        float sA2[4], sB2[4];
        #pragma unroll
        for (int i = 0; i < 4; i++) {
            sA2[i] = sA1[2 * i] + __shfl_xor_sync(0xffffffffu, sA1[2 * i + 1], 2);
            sB2[i] = sB1[2 * i] + __shfl_xor_sync(0xffffffffu, sB1[2 * i + 1], 2);
        }
        // ---- stage 3 (select) ----
        float sA3[2], sB3[2];
        #pragma unroll
        for (int i = 0; i < 2; i++) {
            float kA = (g & 4) ? sA2[i + 2] : sA2[i];
            float dAs = (g & 4) ? sA2[i] : sA2[i + 2];
            sA3[i] = kA + __shfl_xor_sync(0xffffffffu, dAs, 4);
            float kB = (g & 4) ? sB2[i + 2] : sB2[i];
            float dBs = (g & 4) ? sB2[i] : sB2[i + 2];
            sB3[i] = kB + __shfl_xor_sync(0xffffffffu, dBs, 4);
        }
        // ---- stage 4 (select) ----
        float kA = (g & 8) ? sA3[1] : sA3[0];
        float sA = (g & 8) ? sA3[0] : sA3[1];
        float dA = kA + __shfl_xor_sync(0xffffffffu, sA, 8);
        float kB = (g & 8) ? sB3[1] : sB3[0];
        float sB = (g & 8) ? sB3[0] : sB3[1];
        float dB = kB + __shfl_xor_sync(0xffffffffu, sB, 8);

        // |d| <= 1 (unit capsules): exp safe without max-subtraction
        *(float2*)&d_s[grp][c * 36 + 2 * qf] = make_float2(__expf(dA), __expf(dB));
        asm volatile("bar.sync %0, %1;" :: "r"(bid), "r"(128) : "memory");

        // ---- softmax over c (8 adjacent lanes), thread = (m0, cA) ----
        float f0 = d_s[grp][cA * 36 + m0];
        float f1 = d_s[grp][cA * 36 + m0 + 16];
        float sm0 = f0, sm1 = f1;
        sm0 += __shfl_xor_sync(0xffffffffu, sm0, 1);
        sm1 += __shfl_xor_sync(0xffffffffu, sm1, 1);
        sm0 += __shfl_xor_sync(0xffffffffu, sm0, 2);
        sm1 += __shfl_xor_sync(0xffffffffu, sm1, 2);
        sm0 += __shfl_xor_sync(0xffffffffu, sm0, 4);
        sm1 += __shfl_xor_sync(0xffffffffu, sm1, 4);
        ps[grp][cA * 36 + m0]      = __fdividef(f0, sm0);
        ps[grp][cA * 36 + m0 + 16] = __fdividef(f1, sm1);
        asm volatile("bar.sync %0, %1;" :: "r"(bid), "r"(128) : "memory");

        // ---- phase B: u = xc + sum_m p[m,c]*nb[m,c,k], permuted pairing ----
        // ps pair for slot j is (2*(j^(g&3)) .. +1) to match permuted registers;
        // j^(g&3) only relabels which j reads which pair — sum is unchanged.
        float c0 = 0.f, c1 = 0.f, c2 = 0.f, c3 = 0.f;
        #pragma unroll
        for (int j = 0; j < 4; j++) {
            float2 pA = *(const float2*)&ps[grp][c * 36 + 2 * (j ^ (g & 3))];
            c0 = fmaf(pA.x, nbrA[j], c0);
            c1 = fmaf(pA.y, nbrB[j], c1);
            float2 pB = *(const float2*)&ps[grp][c * 36 + 2 * ((j + 4) ^ (g & 3))];
            c2 = fmaf(pB.x, nbrA[j + 4], c2);
            c3 = fmaf(pB.y, nbrB[j + 4], c3);
        }
        #pragma unroll
        for (int j = 8; j < 12; j++) {
            float2 pA = *(const float2*)&ps[grp][c * 36 + 2 * (j ^ (g & 3))];
            c0 = fmaf(pA.x, nbrA[j], c0);
            c1 = fmaf(pA.y, nbrB[j], c1);
            float2 pB = *(const float2*)&ps[grp][c * 36 + 2 * ((j + 4) ^ (g & 3))];
            c2 = fmaf(pB.x, nbrA[j + 4], c2);
            c3 = fmaf(pB.y, nbrB[j + 4], c3);
        }
        acc = xc + ((c0 + c1) + (c2 + c3));

        if (it < 2) {
            float sq = acc * acc;
            sq += __shfl_xor_sync(0xffffffffu, sq, 1);
            sq += __shfl_xor_sync(0xffffffffu, sq, 2);
            sq += __shfl_xor_sync(0xffffffffu, sq, 4);
            sq += __shfl_xor_sync(0xffffffffu, sq, 8);
            u_val = acc * rsqrtf(fmaxf(sq, 1e-24f));
        } else {
            out[(size_t)node * D + tl] = acc;
        }
    }
}

// ---------------------------------------------------------------------------
extern "C" void kernel_launch(void* const* d_in, const int* in_sizes, int n_in,
                              void* d_out, int out_size) {
    const float* x = (const float*)d_in[0];
    const float* W = (const float*)d_in[1];
    const float* b = (const float*)d_in[2];
    const void*  nid = d_in[3];
    float* out = (float*)d_out;

    int n = in_sizes[0] / D;

    static const size_t FC_SMEM = (size_t)(128 * 132 + 32 * 128) * sizeof(float);
    cudaFuncSetAttribute(k_fc, cudaFuncAttributeMaxDynamicSharedMemorySize,
                         (int)FC_SMEM);

    k_init<<<1, 160>>>((const int*)nid, n);
    int nblk = (n + 31) / 32;
    k_fc<<<nblk, 128, FC_SMEM>>>(x, W, b, n);
    k_route<<<(n + 1) / 2, 256>>>(nid, out, n);
}